// round 7
// baseline (speedup 1.0000x reference)
#include <cuda_runtime.h>
#include <cstdint>
#include <math.h>

#define B_   64
#define S_   1024
#define I_   256
#define H_   512
#define O_   512
#define G3H  1536

#define GR    96     // 3 groups x 32 CTAs, all resident (1 CTA/SM via smem)
#define RT    128    // 4 warps, 1 per SMSP
#define STEPS 1026

typedef unsigned long long u64;

// ---------------------------------------------------------------------------
// Device-global scratch
// ---------------------------------------------------------------------------
__device__ float    g_gi0  [(size_t)S_ * G3H * B_];   // gi0 [t][row][b]
__device__ float    g_gi1  [2 * G3H * B_];            // gi1 ring [slot][row][b]
__device__ float    g_h1sq [(size_t)S_ * H_ * B_];    // hseq1 transposed [t][j][b]
__device__ float    g_h0T  [2 * H_ * B_];             // h0 double buffer [slot][j][b]
__device__ float    g_h1T  [2 * H_ * B_];             // h1 double buffer [slot][j][b]
__device__ unsigned g_sync [512];                     // [g*32] grp ctr, [400] root, [416] release

// ---------------------------------------------------------------------------
// f32x2 + cp.async helpers
// ---------------------------------------------------------------------------
__device__ __forceinline__ u64 pk2(float x) {
    u64 r; asm("mov.b64 %0, {%1, %1};" : "=l"(r) : "r"(__float_as_uint(x))); return r;
}
__device__ __forceinline__ void fma2(u64& d, u64 a, u64 b) {
    asm("fma.rn.f32x2 %0, %1, %2, %0;" : "+l"(d) : "l"(a), "l"(b));
}
__device__ __forceinline__ float2 up2(u64 u) {
    unsigned lo, hi; asm("mov.b64 {%0, %1}, %2;" : "=r"(lo), "=r"(hi) : "l"(u));
    return make_float2(__uint_as_float(lo), __uint_as_float(hi));
}
__device__ __forceinline__ void cpa16(float* smem, const float* g) {
    unsigned s = (unsigned)__cvta_generic_to_shared(smem);
    asm volatile("cp.async.cg.shared.global [%0], [%1], 16;" :: "r"(s), "l"(g));
}
__device__ __forceinline__ float sigmoidf_(float x) { return 1.f / (1.f + expf(-x)); }

// ---------------------------------------------------------------------------
// SGEMM + bias. MODE 0: C=A@Bw^T, A=x rows m=b*S+s, out -> gi layout [t][n][b].
// MODE 3: A is transposed-per-t hseq1T [t][k][b] (rows m=t*64+b), out[b][t][n].
// BM=128 BN=64 BK=16, 256 thr, f32x2 mainloop.
// ---------------------------------------------------------------------------
template <int MODE>
__global__ void __launch_bounds__(256)
sgemm_bias(const float* __restrict__ A, const float* __restrict__ Bw,
           const float* __restrict__ bias, float* __restrict__ out,
           int M, int N, int K)
{
    __shared__ float As[16][132];
    __shared__ float Bs[16][68];

    const int tid = threadIdx.x;
    const int m0  = blockIdx.y * 128;
    const int n0  = blockIdx.x * 64;
    const int tx  = tid & 15;
    const int ty  = tid >> 4;

    const float* Bb = Bw + (size_t)n0 * K;

    u64 acc[4][4];
#pragma unroll
    for (int i = 0; i < 4; i++)
#pragma unroll
        for (int j = 0; j < 4; j++) acc[i][j] = 0ull;

    const int lr = tid >> 2;
    const int lk = (tid & 3) * 4;
    const int t0 = m0 >> 6;             // MODE 3
    const int kk = tid >> 4, qq = tid & 15;

    for (int kt = 0; kt < K; kt += 16) {
        if (MODE == 0) {
            const float* Ab = A + (size_t)m0 * K;
#pragma unroll
            for (int p = 0; p < 2; p++) {
                float4 v = *(const float4*)&Ab[(size_t)(lr + p * 64) * K + kt + lk];
                As[lk + 0][lr + p * 64] = v.x;
                As[lk + 1][lr + p * 64] = v.y;
                As[lk + 2][lr + p * 64] = v.z;
                As[lk + 3][lr + p * 64] = v.w;
            }
        } else {
            float4 v0 = *(const float4*)&A[(((size_t)t0       * 512) + kt + kk) * 64 + qq * 4];
            float4 v1 = *(const float4*)&A[(((size_t)(t0 + 1) * 512) + kt + kk) * 64 + qq * 4];
            *(float4*)&As[kk][qq * 4]      = v0;
            *(float4*)&As[kk][64 + qq * 4] = v1;
        }
        {
            float4 v = *(const float4*)&Bb[(size_t)lr * K + kt + lk];
            Bs[lk + 0][lr] = v.x;
            Bs[lk + 1][lr] = v.y;
            Bs[lk + 2][lr] = v.z;
            Bs[lk + 3][lr] = v.w;
        }
        __syncthreads();

#pragma unroll
        for (int k = 0; k < 16; k++) {
            float4 bv = *(const float4*)&Bs[k][tx * 4];
            u64 bp0 = pk2(bv.x), bp1 = pk2(bv.y), bp2 = pk2(bv.z), bp3 = pk2(bv.w);
            ulonglong2 a01 = *(const ulonglong2*)&As[k][ty * 8];
            ulonglong2 a23 = *(const ulonglong2*)&As[k][ty * 8 + 4];
            u64 ap[4] = {a01.x, a01.y, a23.x, a23.y};
#pragma unroll
            for (int i = 0; i < 4; i++) {
                fma2(acc[i][0], ap[i], bp0);
                fma2(acc[i][1], ap[i], bp1);
                fma2(acc[i][2], ap[i], bp2);
                fma2(acc[i][3], ap[i], bp3);
            }
        }
        __syncthreads();
    }

    float accf[8][4];
#pragma unroll
    for (int i = 0; i < 4; i++)
#pragma unroll
        for (int j = 0; j < 4; j++) {
            float2 v = up2(acc[i][j]);
            accf[2 * i + 0][j] = v.x;
            accf[2 * i + 1][j] = v.y;
        }

    float bv[4];
    *(float4*)bv = *(const float4*)&bias[n0 + tx * 4];

#pragma unroll
    for (int i = 0; i < 8; i++) {
        int m = m0 + ty * 8 + i;
        if (MODE == 3) {
            int t = m >> 6, b = m & 63;
            float4 c;
            c.x = accf[i][0] + bv[0];
            c.y = accf[i][1] + bv[1];
            c.z = accf[i][2] + bv[2];
            c.w = accf[i][3] + bv[3];
            *(float4*)&out[((size_t)b * S_ + t) * O_ + n0 + tx * 4] = c;
        } else {
            int t = m & (S_ - 1), b = m >> 10;
#pragma unroll
            for (int j = 0; j < 4; j++)
                out[((size_t)t * G3H + n0 + tx * 4 + j) * B_ + b] = accf[i][j] + bv[j];
        }
    }
}

// ---------------------------------------------------------------------------
// Fused two-layer GRU wavefront. 96 CTAs = 3 groups x 32.
//  G0: h0[s]    = cell(h0[s-1], gi0[s])          s in [0,1023]
//  G1: gi1[s-1] = h0[s-1] @ W_ih1^T + b_ih1      s in [1,1024]
//  G2: h1[s-2]  = cell(h1[s-3], gi1[s-2])        s in [2,1025]
// CTA slice: 16 j x 3 gates x 512 k x 64 b; weights resident in smem (96KB);
// full source-h staged per step via 4 pipelined cp.async chunk groups (128KB).
// Thread = (jl, 8 b): owns all 3 gate accumulators -> no cross-thread reduce.
// smem floats: hs[512*64] @0 | Wrz(float2)[512*16] @32768 | Wn[512*16] @49152
// ---------------------------------------------------------------------------
#define FUS_SMEM_BYTES (57344 * 4)

template <int C>
__device__ __forceinline__ void do_chunk(const float* __restrict__ hs,
                                         const float2* __restrict__ Wrz,
                                         const float* __restrict__ Wn,
                                         int jl, int b0,
                                         u64* aR, u64* aZ, u64* aN)
{
    asm volatile("cp.async.wait_group %0;" :: "n"(3 - C));
    __syncthreads();
#pragma unroll 8
    for (int k = C * 128; k < C * 128 + 128; k++) {
        float2 wrz = Wrz[k * 16 + jl];
        float  wnf = Wn [k * 16 + jl];
        u64 wr = pk2(wrz.x), wz = pk2(wrz.y), wn = pk2(wnf);
        ulonglong2 hA = *(const ulonglong2*)&hs[k * 64 + b0];
        ulonglong2 hB = *(const ulonglong2*)&hs[k * 64 + b0 + 4];
        fma2(aR[0], hA.x, wr); fma2(aR[1], hA.y, wr);
        fma2(aR[2], hB.x, wr); fma2(aR[3], hB.y, wr);
        fma2(aZ[0], hA.x, wz); fma2(aZ[1], hA.y, wz);
        fma2(aZ[2], hB.x, wz); fma2(aZ[3], hB.y, wz);
        fma2(aN[0], hA.x, wn); fma2(aN[1], hA.y, wn);
        fma2(aN[2], hB.x, wn); fma2(aN[3], hB.y, wn);
    }
}

__global__ void __launch_bounds__(RT, 1)
gru_fused(const float* __restrict__ gi0,
          const float* __restrict__ Whh0, const float* __restrict__ bhh0,
          const float* __restrict__ Wih1, const float* __restrict__ bih1,
          const float* __restrict__ Whh1, const float* __restrict__ bhh1,
          float* __restrict__ hid)    // [2][B][H] tail of d_out
{
    extern __shared__ float sm[];
    float*  hs  = sm;
    float2* Wrz = (float2*)(sm + 32768);
    float*  Wn  = sm + 49152;

    const int tid   = threadIdx.x;
    const int cta   = blockIdx.x;
    const int grp   = cta >> 5;
    const int lc    = cta & 31;
    const int jbase = lc * 16;

    const float* Wsrc = (grp == 0) ? Whh0 : (grp == 1) ? Wih1 : Whh1;

    // Weight slice preload: rows (j, 512+j, 1024+j) for 16 j, k-major in smem.
    for (int i = tid; i < 16 * 512; i += RT) {
        int k = i & 511, jj = i >> 9;
        int j = jbase + jj;
        float wr = Wsrc[(size_t)j          * 512 + k];
        float wz = Wsrc[(size_t)(512 + j)  * 512 + k];
        float wn = Wsrc[(size_t)(1024 + j) * 512 + k];
        Wrz[k * 16 + jj] = make_float2(wr, wz);
        Wn [k * 16 + jj] = wn;
    }

    const int jl = tid >> 3;       // 0..15
    const int b0 = (tid & 7) * 8;  // 8 batch per thread
    const int j  = jbase + jl;

    float br = 0.f, bz = 0.f, bn = 0.f;
    if (grp == 0) { br = bhh0[j]; bz = bhh0[512 + j]; bn = bhh0[1024 + j]; }
    if (grp == 1) { br = bih1[j]; bz = bih1[512 + j]; bn = bih1[1024 + j]; }
    if (grp == 2) { br = bhh1[j]; bz = bhh1[512 + j]; bn = bhh1[1024 + j]; }

    __syncthreads();

    for (int s = 0; s < STEPS; s++) {
        const bool active = (grp == 0) ? (s < 1024)
                          : (grp == 1) ? (s >= 1 && s < 1025)
                                       : (s >= 2);
        if (active) {
            const float* hsrc = ((grp == 2) ? g_h1T : g_h0T)
                              + (((grp == 2 ? s - 2 : s) + 1) & 1) * (H_ * B_);

            // Issue 4 chunk groups (32 KB each) of the full source-h state
#pragma unroll
            for (int c = 0; c < 4; c++) {
                const float* s4 = hsrc + c * 8192;
                float*       d4 = hs   + c * 8192;
#pragma unroll
                for (int u = 0; u < 16; u++)
                    cpa16(d4 + (tid + u * RT) * 4, s4 + (tid + u * RT) * 4);
                asm volatile("cp.async.commit_group;");
            }

            // Prefetch gi into registers (hidden under mainloop)
            float GIR[8], GIZ[8], GIN[8];
            if (grp != 1) {
                const float* p = (grp == 0)
                    ? gi0   + (size_t)s * (G3H * 64)
                    : g_gi1 + (size_t)(s & 1) * (G3H * 64);
                *(float4*)&GIR[0] = *(const float4*)&p[(size_t)j          * 64 + b0];
                *(float4*)&GIR[4] = *(const float4*)&p[(size_t)j          * 64 + b0 + 4];
                *(float4*)&GIZ[0] = *(const float4*)&p[(size_t)(512 + j)  * 64 + b0];
                *(float4*)&GIZ[4] = *(const float4*)&p[(size_t)(512 + j)  * 64 + b0 + 4];
                *(float4*)&GIN[0] = *(const float4*)&p[(size_t)(1024 + j) * 64 + b0];
                *(float4*)&GIN[4] = *(const float4*)&p[(size_t)(1024 + j) * 64 + b0 + 4];
            }

            u64 aR[4] = {0,0,0,0}, aZ[4] = {0,0,0,0}, aN[4] = {0,0,0,0};
            do_chunk<0>(hs, Wrz, Wn, jl, b0, aR, aZ, aN);
            do_chunk<1>(hs, Wrz, Wn, jl, b0, aR, aZ, aN);
            do_chunk<2>(hs, Wrz, Wn, jl, b0, aR, aZ, aN);
            do_chunk<3>(hs, Wrz, Wn, jl, b0, aR, aZ, aN);

            float R[8], Z[8], N[8];
#pragma unroll
            for (int p = 0; p < 4; p++) {
                float2 r = up2(aR[p]), z = up2(aZ[p]), n = up2(aN[p]);
                R[2*p] = r.x; R[2*p+1] = r.y;
                Z[2*p] = z.x; Z[2*p+1] = z.y;
                N[2*p] = n.x; N[2*p+1] = n.y;
            }

            if (grp == 1) {
                float* q = g_gi1 + (size_t)((s - 1) & 1) * (G3H * 64);
                float o[8];
#pragma unroll
                for (int i = 0; i < 8; i++) o[i] = R[i] + br;
                *(float4*)&q[(size_t)j * 64 + b0]     = *(float4*)&o[0];
                *(float4*)&q[(size_t)j * 64 + b0 + 4] = *(float4*)&o[4];
#pragma unroll
                for (int i = 0; i < 8; i++) o[i] = Z[i] + bz;
                *(float4*)&q[(size_t)(512 + j) * 64 + b0]     = *(float4*)&o[0];
                *(float4*)&q[(size_t)(512 + j) * 64 + b0 + 4] = *(float4*)&o[4];
#pragma unroll
                for (int i = 0; i < 8; i++) o[i] = N[i] + bn;
                *(float4*)&q[(size_t)(1024 + j) * 64 + b0]     = *(float4*)&o[0];
                *(float4*)&q[(size_t)(1024 + j) * 64 + b0 + 4] = *(float4*)&o[4];
            } else {
                float hold[8];
                *(float4*)&hold[0] = *(const float4*)&hs[j * 64 + b0];
                *(float4*)&hold[4] = *(const float4*)&hs[j * 64 + b0 + 4];

                float hn[8];
#pragma unroll
                for (int i = 0; i < 8; i++) {
                    float r_ = sigmoidf_(GIR[i] + R[i] + br);
                    float z_ = sigmoidf_(GIZ[i] + Z[i] + bz);
                    float n_ = tanhf(GIN[i] + r_ * (N[i] + bn));
                    hn[i] = (1.f - z_) * n_ + z_ * hold[i];
                }

                const int tau = (grp == 2) ? s - 2 : s;
                float* hdT = ((grp == 2) ? g_h1T : g_h0T) + (tau & 1) * (H_ * B_);
                *(float4*)&hdT[j * 64 + b0]     = *(float4*)&hn[0];
                *(float4*)&hdT[j * 64 + b0 + 4] = *(float4*)&hn[4];

                if (grp == 2) {
                    float* hq = g_h1sq + (size_t)tau * (H_ * B_);
                    *(float4*)&hq[j * 64 + b0]     = *(float4*)&hn[0];
                    *(float4*)&hq[j * 64 + b0 + 4] = *(float4*)&hn[4];
                }
                if (tau == S_ - 1) {
                    float* hd = hid + (grp == 2 ? B_ * H_ : 0);
#pragma unroll
                    for (int i = 0; i < 8; i++)
                        hd[(size_t)(b0 + i) * H_ + j] = hn[i];
                }
            }
        }

        // ---- two-level grid barrier ----
        if (tid == 0) {
            __threadfence();
            unsigned go = atomicAdd(&g_sync[(cta >> 3) * 32], 1u);
            if (go == (unsigned)(s + 1) * 8 - 1) {
                unsigned ro = atomicAdd(&g_sync[400], 1u);
                if (ro == (unsigned)(s + 1) * 12 - 1) {
                    __threadfence();
                    *((volatile unsigned*)&g_sync[416]) = (unsigned)(s + 1);
                }
            }
            while (*((volatile unsigned*)&g_sync[416]) < (unsigned)(s + 1)) { }
            __threadfence();
        }
        __syncthreads();
    }
}

// ---------------------------------------------------------------------------
// Launch
// ---------------------------------------------------------------------------
extern "C" void kernel_launch(void* const* d_in, const int* in_sizes, int n_in,
                              void* d_out, int out_size)
{
    const float* x    = (const float*)d_in[0];
    const float* Wih0 = (const float*)d_in[1];
    const float* Whh0 = (const float*)d_in[2];
    const float* bih0 = (const float*)d_in[3];
    const float* bhh0 = (const float*)d_in[4];
    const float* Wih1 = (const float*)d_in[5];
    const float* Whh1 = (const float*)d_in[6];
    const float* bih1 = (const float*)d_in[7];
    const float* bhh1 = (const float*)d_in[8];
    const float* Wfc  = (const float*)d_in[9];
    const float* bfc  = (const float*)d_in[10];

    float* out = (float*)d_out;                    // logits [B][S][O]
    float* hid = out + (size_t)B_ * S_ * O_;       // hidden [2][B][H]

    float *gi0, *h1sq, *h0T, *h1T;
    unsigned* sy;
    cudaGetSymbolAddress((void**)&gi0,  g_gi0);
    cudaGetSymbolAddress((void**)&h1sq, g_h1sq);
    cudaGetSymbolAddress((void**)&h0T,  g_h0T);
    cudaGetSymbolAddress((void**)&h1T,  g_h1T);
    cudaGetSymbolAddress((void**)&sy,   g_sync);

    cudaFuncSetAttribute(gru_fused, cudaFuncAttributeMaxDynamicSharedMemorySize,
                         FUS_SMEM_BYTES);

    const int M = B_ * S_;
    dim3 blk(256);
    dim3 gGI(G3H / 64, M / 128);   // 24 x 512
    dim3 gFC(O_ / 64, M / 128);    //  8 x 512

    // gi0 = x @ W_ih0^T + b_ih0   -> [t][row][b]
    sgemm_bias<0><<<gGI, blk>>>(x, Wih0, bih0, gi0, M, G3H, I_);

    cudaMemsetAsync(h0T, 0, (size_t)2 * H_ * B_ * sizeof(float));
    cudaMemsetAsync(h1T, 0, (size_t)2 * H_ * B_ * sizeof(float));
    cudaMemsetAsync(sy, 0, 512 * sizeof(unsigned));

    gru_fused<<<GR, RT, FUS_SMEM_BYTES>>>(gi0, Whh0, bhh0, Wih1, bih1,
                                          Whh1, bhh1, hid);

    // logits = hseq1 @ W_fc^T + b_fc   (A read from transposed [t][j][b])
    sgemm_bias<3><<<gFC, blk>>>(h1sq, Wfc, bfc, out, M, O_, H_);
}

// round 8
// speedup vs baseline: 1.2800x; 1.2800x over previous
#include <cuda_runtime.h>
#include <cstdint>
#include <math.h>

#define B_   64
#define S_   1024
#define I_   256
#define H_   512
#define O_   512
#define G3H  1536

#define GR    96     // 3 groups x 32 CTAs, all resident (1 CTA/SM via smem)
#define RT    256    // 8 warps -> 2 per SMSP (latency hiding)
#define STEPS 1026

typedef unsigned long long u64;

// ---------------------------------------------------------------------------
// Device-global scratch
// ---------------------------------------------------------------------------
__device__ float    g_gi0  [(size_t)S_ * G3H * B_];   // gi0 [t][row][b]
__device__ float    g_gi1  [2 * G3H * B_];            // gi1 ring [slot][row][b]
__device__ float    g_h1sq [(size_t)S_ * H_ * B_];    // hseq1 transposed [t][j][b]
__device__ float    g_h0T  [2 * H_ * B_];             // h0 double buffer [slot][j][b]
__device__ float    g_h1T  [2 * H_ * B_];             // h1 double buffer [slot][j][b]
__device__ unsigned g_sync [512];                     // [g*32] grp ctr, [400] root, [416] release

// ---------------------------------------------------------------------------
// f32x2 + cp.async helpers
// ---------------------------------------------------------------------------
__device__ __forceinline__ u64 pk2(float x) {
    u64 r; asm("mov.b64 %0, {%1, %1};" : "=l"(r) : "r"(__float_as_uint(x))); return r;
}
__device__ __forceinline__ void fma2(u64& d, u64 a, u64 b) {
    asm("fma.rn.f32x2 %0, %1, %2, %0;" : "+l"(d) : "l"(a), "l"(b));
}
__device__ __forceinline__ float2 up2(u64 u) {
    unsigned lo, hi; asm("mov.b64 {%0, %1}, %2;" : "=r"(lo), "=r"(hi) : "l"(u));
    return make_float2(__uint_as_float(lo), __uint_as_float(hi));
}
__device__ __forceinline__ void cpa16(float* smem, const float* g) {
    unsigned s = (unsigned)__cvta_generic_to_shared(smem);
    asm volatile("cp.async.cg.shared.global [%0], [%1], 16;" :: "r"(s), "l"(g));
}
__device__ __forceinline__ float sigmoidf_(float x) { return 1.f / (1.f + expf(-x)); }

// ---------------------------------------------------------------------------
// SGEMM + bias. MODE 0: C=A@Bw^T, A=x rows m=b*S+s, out -> gi layout [t][n][b].
// MODE 3: A is transposed-per-t hseq1T [t][k][b] (rows m=t*64+b), out[b][t][n].
// BM=128 BN=64 BK=16, 256 thr, f32x2 mainloop.
// ---------------------------------------------------------------------------
template <int MODE>
__global__ void __launch_bounds__(256)
sgemm_bias(const float* __restrict__ A, const float* __restrict__ Bw,
           const float* __restrict__ bias, float* __restrict__ out,
           int M, int N, int K)
{
    __shared__ float As[16][132];
    __shared__ float Bs[16][68];

    const int tid = threadIdx.x;
    const int m0  = blockIdx.y * 128;
    const int n0  = blockIdx.x * 64;
    const int tx  = tid & 15;
    const int ty  = tid >> 4;

    const float* Bb = Bw + (size_t)n0 * K;

    u64 acc[4][4];
#pragma unroll
    for (int i = 0; i < 4; i++)
#pragma unroll
        for (int j = 0; j < 4; j++) acc[i][j] = 0ull;

    const int lr = tid >> 2;
    const int lk = (tid & 3) * 4;
    const int t0 = m0 >> 6;             // MODE 3
    const int kk = tid >> 4, qq = tid & 15;

    for (int kt = 0; kt < K; kt += 16) {
        if (MODE == 0) {
            const float* Ab = A + (size_t)m0 * K;
#pragma unroll
            for (int p = 0; p < 2; p++) {
                float4 v = *(const float4*)&Ab[(size_t)(lr + p * 64) * K + kt + lk];
                As[lk + 0][lr + p * 64] = v.x;
                As[lk + 1][lr + p * 64] = v.y;
                As[lk + 2][lr + p * 64] = v.z;
                As[lk + 3][lr + p * 64] = v.w;
            }
        } else {
            float4 v0 = *(const float4*)&A[(((size_t)t0       * 512) + kt + kk) * 64 + qq * 4];
            float4 v1 = *(const float4*)&A[(((size_t)(t0 + 1) * 512) + kt + kk) * 64 + qq * 4];
            *(float4*)&As[kk][qq * 4]      = v0;
            *(float4*)&As[kk][64 + qq * 4] = v1;
        }
        {
            float4 v = *(const float4*)&Bb[(size_t)lr * K + kt + lk];
            Bs[lk + 0][lr] = v.x;
            Bs[lk + 1][lr] = v.y;
            Bs[lk + 2][lr] = v.z;
            Bs[lk + 3][lr] = v.w;
        }
        __syncthreads();

#pragma unroll
        for (int k = 0; k < 16; k++) {
            float4 bv = *(const float4*)&Bs[k][tx * 4];
            u64 bp0 = pk2(bv.x), bp1 = pk2(bv.y), bp2 = pk2(bv.z), bp3 = pk2(bv.w);
            ulonglong2 a01 = *(const ulonglong2*)&As[k][ty * 8];
            ulonglong2 a23 = *(const ulonglong2*)&As[k][ty * 8 + 4];
            u64 ap[4] = {a01.x, a01.y, a23.x, a23.y};
#pragma unroll
            for (int i = 0; i < 4; i++) {
                fma2(acc[i][0], ap[i], bp0);
                fma2(acc[i][1], ap[i], bp1);
                fma2(acc[i][2], ap[i], bp2);
                fma2(acc[i][3], ap[i], bp3);
            }
        }
        __syncthreads();
    }

    float accf[8][4];
#pragma unroll
    for (int i = 0; i < 4; i++)
#pragma unroll
        for (int j = 0; j < 4; j++) {
            float2 v = up2(acc[i][j]);
            accf[2 * i + 0][j] = v.x;
            accf[2 * i + 1][j] = v.y;
        }

    float bv[4];
    *(float4*)bv = *(const float4*)&bias[n0 + tx * 4];

#pragma unroll
    for (int i = 0; i < 8; i++) {
        int m = m0 + ty * 8 + i;
        if (MODE == 3) {
            int t = m >> 6, b = m & 63;
            float4 c;
            c.x = accf[i][0] + bv[0];
            c.y = accf[i][1] + bv[1];
            c.z = accf[i][2] + bv[2];
            c.w = accf[i][3] + bv[3];
            *(float4*)&out[((size_t)b * S_ + t) * O_ + n0 + tx * 4] = c;
        } else {
            int t = m & (S_ - 1), b = m >> 10;
#pragma unroll
            for (int j = 0; j < 4; j++)
                out[((size_t)t * G3H + n0 + tx * 4 + j) * B_ + b] = accf[i][j] + bv[j];
        }
    }
}

// ---------------------------------------------------------------------------
// Fused two-layer GRU wavefront. 96 CTAs = 3 groups x 32.
//  G0: h0[s]    = cell(h0[s-1], gi0[s])          s in [0,1023]
//  G1: gi1[s-1] = h0[s-1] @ W_ih1^T + b_ih1      s in [1,1024]
//  G2: h1[s-2]  = cell(h1[s-3], gi1[s-2])        s in [2,1025]
// CTA slice: 16 j x 3 gates x 512 k x 64 b; weights resident in smem (96KB);
// full source-h staged per step via 4 pipelined cp.async chunk groups (128KB).
// Thread = (jl, 4 b): owns all 3 gate accumulators -> no cross-thread reduce.
// smem floats: hs[512*64] @0 | Wrz(float2)[512*16] @32768 | Wn[512*16] @49152
// ---------------------------------------------------------------------------
#define FUS_SMEM_BYTES (57344 * 4)

template <int C>
__device__ __forceinline__ void do_chunk(const float* __restrict__ hs,
                                         const float2* __restrict__ Wrz,
                                         const float* __restrict__ Wn,
                                         int jl, int b0,
                                         u64* aR, u64* aZ, u64* aN)
{
    asm volatile("cp.async.wait_group %0;" :: "n"(3 - C));
    __syncthreads();
#pragma unroll 4
    for (int k = C * 128; k < C * 128 + 128; k++) {
        float2 wrz = Wrz[k * 16 + jl];
        float  wnf = Wn [k * 16 + jl];
        u64 wr = pk2(wrz.x), wz = pk2(wrz.y), wn = pk2(wnf);
        ulonglong2 h = *(const ulonglong2*)&hs[k * 64 + b0];
        fma2(aR[0], h.x, wr); fma2(aR[1], h.y, wr);
        fma2(aZ[0], h.x, wz); fma2(aZ[1], h.y, wz);
        fma2(aN[0], h.x, wn); fma2(aN[1], h.y, wn);
    }
}

__global__ void __launch_bounds__(RT, 1)
gru_fused(const float* __restrict__ gi0,
          const float* __restrict__ Whh0, const float* __restrict__ bhh0,
          const float* __restrict__ Wih1, const float* __restrict__ bih1,
          const float* __restrict__ Whh1, const float* __restrict__ bhh1,
          float* __restrict__ hid)    // [2][B][H] tail of d_out
{
    extern __shared__ float sm[];
    float*  hs  = sm;
    float2* Wrz = (float2*)(sm + 32768);
    float*  Wn  = sm + 49152;

    const int tid   = threadIdx.x;
    const int cta   = blockIdx.x;
    const int grp   = cta >> 5;
    const int lc    = cta & 31;
    const int jbase = lc * 16;

    const float* Wsrc = (grp == 0) ? Whh0 : (grp == 1) ? Wih1 : Whh1;

    // Weight slice preload: rows (j, 512+j, 1024+j) for 16 j, k-major in smem.
    for (int i = tid; i < 16 * 512; i += RT) {
        int k = i & 511, jj = i >> 9;
        int j = jbase + jj;
        float wr = Wsrc[(size_t)j          * 512 + k];
        float wz = Wsrc[(size_t)(512 + j)  * 512 + k];
        float wn = Wsrc[(size_t)(1024 + j) * 512 + k];
        Wrz[k * 16 + jj] = make_float2(wr, wz);
        Wn [k * 16 + jj] = wn;
    }

    const int jl = tid >> 4;       // 0..15
    const int b0 = (tid & 15) * 4; // 4 batch per thread
    const int j  = jbase + jl;

    float br = 0.f, bz = 0.f, bn = 0.f;
    if (grp == 0) { br = bhh0[j]; bz = bhh0[512 + j]; bn = bhh0[1024 + j]; }
    if (grp == 1) { br = bih1[j]; bz = bih1[512 + j]; bn = bih1[1024 + j]; }
    if (grp == 2) { br = bhh1[j]; bz = bhh1[512 + j]; bn = bhh1[1024 + j]; }

    __syncthreads();

    for (int s = 0; s < STEPS; s++) {
        const bool active = (grp == 0) ? (s < 1024)
                          : (grp == 1) ? (s >= 1 && s < 1025)
                                       : (s >= 2);
        if (active) {
            const float* hsrc = ((grp == 2) ? g_h1T : g_h0T)
                              + (((grp == 2 ? s - 2 : s) + 1) & 1) * (H_ * B_);

            // Issue 4 chunk groups (32 KB each) of the full source-h state
#pragma unroll
            for (int c = 0; c < 4; c++) {
                const float* s4 = hsrc + c * 8192;
                float*       d4 = hs   + c * 8192;
#pragma unroll
                for (int u = 0; u < 8; u++)
                    cpa16(d4 + (tid + u * RT) * 4, s4 + (tid + u * RT) * 4);
                asm volatile("cp.async.commit_group;");
            }

            // Prefetch gi into registers (hidden under mainloop)
            float GIR[4], GIZ[4], GIN[4];
            if (grp != 1) {
                const float* p = (grp == 0)
                    ? gi0   + (size_t)s * (G3H * 64)
                    : g_gi1 + (size_t)(s & 1) * (G3H * 64);
                *(float4*)&GIR[0] = *(const float4*)&p[(size_t)j          * 64 + b0];
                *(float4*)&GIZ[0] = *(const float4*)&p[(size_t)(512 + j)  * 64 + b0];
                *(float4*)&GIN[0] = *(const float4*)&p[(size_t)(1024 + j) * 64 + b0];
            }

            u64 aR[2] = {0, 0}, aZ[2] = {0, 0}, aN[2] = {0, 0};
            do_chunk<0>(hs, Wrz, Wn, jl, b0, aR, aZ, aN);
            do_chunk<1>(hs, Wrz, Wn, jl, b0, aR, aZ, aN);
            do_chunk<2>(hs, Wrz, Wn, jl, b0, aR, aZ, aN);
            do_chunk<3>(hs, Wrz, Wn, jl, b0, aR, aZ, aN);

            float R[4], Z[4], N[4];
#pragma unroll
            for (int p = 0; p < 2; p++) {
                float2 r = up2(aR[p]), z = up2(aZ[p]), n = up2(aN[p]);
                R[2*p] = r.x; R[2*p+1] = r.y;
                Z[2*p] = z.x; Z[2*p+1] = z.y;
                N[2*p] = n.x; N[2*p+1] = n.y;
            }

            if (grp == 1) {
                float* q = g_gi1 + (size_t)((s - 1) & 1) * (G3H * 64);
                float o[4];
#pragma unroll
                for (int i = 0; i < 4; i++) o[i] = R[i] + br;
                *(float4*)&q[(size_t)j * 64 + b0] = *(float4*)&o[0];
#pragma unroll
                for (int i = 0; i < 4; i++) o[i] = Z[i] + bz;
                *(float4*)&q[(size_t)(512 + j) * 64 + b0] = *(float4*)&o[0];
#pragma unroll
                for (int i = 0; i < 4; i++) o[i] = N[i] + bn;
                *(float4*)&q[(size_t)(1024 + j) * 64 + b0] = *(float4*)&o[0];
            } else {
                float hold[4];
                *(float4*)&hold[0] = *(const float4*)&hs[j * 64 + b0];

                float hn[4];
#pragma unroll
                for (int i = 0; i < 4; i++) {
                    float r_ = sigmoidf_(GIR[i] + R[i] + br);
                    float z_ = sigmoidf_(GIZ[i] + Z[i] + bz);
                    float n_ = tanhf(GIN[i] + r_ * (N[i] + bn));
                    hn[i] = (1.f - z_) * n_ + z_ * hold[i];
                }

                const int tau = (grp == 2) ? s - 2 : s;
                float* hdT = ((grp == 2) ? g_h1T : g_h0T) + (tau & 1) * (H_ * B_);
                *(float4*)&hdT[j * 64 + b0] = *(float4*)&hn[0];

                if (grp == 2) {
                    float* hq = g_h1sq + (size_t)tau * (H_ * B_);
                    *(float4*)&hq[j * 64 + b0] = *(float4*)&hn[0];
                }
                if (tau == S_ - 1) {
                    float* hd = hid + (grp == 2 ? B_ * H_ : 0);
#pragma unroll
                    for (int i = 0; i < 4; i++)
                        hd[(size_t)(b0 + i) * H_ + j] = hn[i];
                }
            }
        }

        // ---- two-level grid barrier (syncthreads first: makes every thread's
        //      global writes happen-before tid0's release fence) ----
        __syncthreads();
        if (tid == 0) {
            __threadfence();
            unsigned go = atomicAdd(&g_sync[(cta >> 3) * 32], 1u);
            if (go == (unsigned)(s + 1) * 8 - 1) {
                unsigned ro = atomicAdd(&g_sync[400], 1u);
                if (ro == (unsigned)(s + 1) * 12 - 1) {
                    __threadfence();
                    *((volatile unsigned*)&g_sync[416]) = (unsigned)(s + 1);
                }
            }
            while (*((volatile unsigned*)&g_sync[416]) < (unsigned)(s + 1)) { }
            __threadfence();
        }
        __syncthreads();
    }
}

// ---------------------------------------------------------------------------
// Launch
// ---------------------------------------------------------------------------
extern "C" void kernel_launch(void* const* d_in, const int* in_sizes, int n_in,
                              void* d_out, int out_size)
{
    const float* x    = (const float*)d_in[0];
    const float* Wih0 = (const float*)d_in[1];
    const float* Whh0 = (const float*)d_in[2];
    const float* bih0 = (const float*)d_in[3];
    const float* bhh0 = (const float*)d_in[4];
    const float* Wih1 = (const float*)d_in[5];
    const float* Whh1 = (const float*)d_in[6];
    const float* bih1 = (const float*)d_in[7];
    const float* bhh1 = (const float*)d_in[8];
    const float* Wfc  = (const float*)d_in[9];
    const float* bfc  = (const float*)d_in[10];

    float* out = (float*)d_out;                    // logits [B][S][O]
    float* hid = out + (size_t)B_ * S_ * O_;       // hidden [2][B][H]

    float *gi0, *h1sq, *h0T, *h1T;
    unsigned* sy;
    cudaGetSymbolAddress((void**)&gi0,  g_gi0);
    cudaGetSymbolAddress((void**)&h1sq, g_h1sq);
    cudaGetSymbolAddress((void**)&h0T,  g_h0T);
    cudaGetSymbolAddress((void**)&h1T,  g_h1T);
    cudaGetSymbolAddress((void**)&sy,   g_sync);

    cudaFuncSetAttribute(gru_fused, cudaFuncAttributeMaxDynamicSharedMemorySize,
                         FUS_SMEM_BYTES);

    const int M = B_ * S_;
    dim3 blk(256);
    dim3 gGI(G3H / 64, M / 128);   // 24 x 512
    dim3 gFC(O_ / 64, M / 128);    //  8 x 512

    // gi0 = x @ W_ih0^T + b_ih0   -> [t][row][b]
    sgemm_bias<0><<<gGI, blk>>>(x, Wih0, bih0, gi0, M, G3H, I_);

    cudaMemsetAsync(h0T, 0, (size_t)2 * H_ * B_ * sizeof(float));
    cudaMemsetAsync(h1T, 0, (size_t)2 * H_ * B_ * sizeof(float));
    cudaMemsetAsync(sy, 0, 512 * sizeof(unsigned));

    gru_fused<<<GR, RT, FUS_SMEM_BYTES>>>(gi0, Whh0, bhh0, Wih1, bih1,
                                          Whh1, bhh1, hid);

    // logits = hseq1 @ W_fc^T + b_fc   (A read from transposed [t][j][b])
    sgemm_bias<3><<<gFC, blk>>>(h1sq, Wfc, bfc, out, M, O_, H_);
}

// round 9
// speedup vs baseline: 1.2827x; 1.0022x over previous
#include <cuda_runtime.h>
#include <cstdint>
#include <math.h>

#define B_   64
#define S_   1024
#define I_   256
#define H_   512
#define O_   512
#define G3H  1536

#define GR    96     // 3 groups x 32 CTAs, all resident (1 CTA/SM via smem)
#define RT    256    // 8 warps -> 2 per SMSP
#define STEPS 1026

typedef unsigned long long u64;

// ---------------------------------------------------------------------------
// Device-global scratch
// ---------------------------------------------------------------------------
__device__ float    g_gi0  [(size_t)S_ * G3H * B_];   // gi0 [t][row][b]
__device__ float    g_gi1  [2 * G3H * B_];            // gi1 ring [slot][row][b]
__device__ float    g_h1sq [(size_t)S_ * H_ * B_];    // hseq1 transposed [t][j][b]
__device__ float    g_h0T  [2 * H_ * B_];             // h0 double buffer [slot][j][b]
__device__ float    g_h1T  [2 * H_ * B_];             // h1 double buffer [slot][j][b]
__device__ unsigned g_sync [512];                     // [g*32] grp ctr, [400] root, [416] release

// ---------------------------------------------------------------------------
// f32x2 + cp.async helpers
// ---------------------------------------------------------------------------
__device__ __forceinline__ u64 pk2(float x) {
    u64 r; asm("mov.b64 %0, {%1, %1};" : "=l"(r) : "r"(__float_as_uint(x))); return r;
}
__device__ __forceinline__ void fma2(u64& d, u64 a, u64 b) {
    asm("fma.rn.f32x2 %0, %1, %2, %0;" : "+l"(d) : "l"(a), "l"(b));
}
__device__ __forceinline__ void add2(u64& d, u64 a) {
    asm("add.rn.f32x2 %0, %0, %1;" : "+l"(d) : "l"(a));
}
__device__ __forceinline__ float2 up2(u64 u) {
    unsigned lo, hi; asm("mov.b64 {%0, %1}, %2;" : "=r"(lo), "=r"(hi) : "l"(u));
    return make_float2(__uint_as_float(lo), __uint_as_float(hi));
}
__device__ __forceinline__ void cpa16(float* smem, const float* g) {
    unsigned s = (unsigned)__cvta_generic_to_shared(smem);
    asm volatile("cp.async.cg.shared.global [%0], [%1], 16;" :: "r"(s), "l"(g));
}
__device__ __forceinline__ float sigmoidf_(float x) { return 1.f / (1.f + expf(-x)); }

// ---------------------------------------------------------------------------
// SGEMM + bias (unchanged from R7). MODE 0: gi layout. MODE 3: logits layout.
// ---------------------------------------------------------------------------
template <int MODE>
__global__ void __launch_bounds__(256)
sgemm_bias(const float* __restrict__ A, const float* __restrict__ Bw,
           const float* __restrict__ bias, float* __restrict__ out,
           int M, int N, int K)
{
    __shared__ float As[16][132];
    __shared__ float Bs[16][68];

    const int tid = threadIdx.x;
    const int m0  = blockIdx.y * 128;
    const int n0  = blockIdx.x * 64;
    const int tx  = tid & 15;
    const int ty  = tid >> 4;

    const float* Bb = Bw + (size_t)n0 * K;

    u64 acc[4][4];
#pragma unroll
    for (int i = 0; i < 4; i++)
#pragma unroll
        for (int j = 0; j < 4; j++) acc[i][j] = 0ull;

    const int lr = tid >> 2;
    const int lk = (tid & 3) * 4;
    const int t0 = m0 >> 6;
    const int kk = tid >> 4, qq = tid & 15;

    for (int kt = 0; kt < K; kt += 16) {
        if (MODE == 0) {
            const float* Ab = A + (size_t)m0 * K;
#pragma unroll
            for (int p = 0; p < 2; p++) {
                float4 v = *(const float4*)&Ab[(size_t)(lr + p * 64) * K + kt + lk];
                As[lk + 0][lr + p * 64] = v.x;
                As[lk + 1][lr + p * 64] = v.y;
                As[lk + 2][lr + p * 64] = v.z;
                As[lk + 3][lr + p * 64] = v.w;
            }
        } else {
            float4 v0 = *(const float4*)&A[(((size_t)t0       * 512) + kt + kk) * 64 + qq * 4];
            float4 v1 = *(const float4*)&A[(((size_t)(t0 + 1) * 512) + kt + kk) * 64 + qq * 4];
            *(float4*)&As[kk][qq * 4]      = v0;
            *(float4*)&As[kk][64 + qq * 4] = v1;
        }
        {
            float4 v = *(const float4*)&Bb[(size_t)lr * K + kt + lk];
            Bs[lk + 0][lr] = v.x;
            Bs[lk + 1][lr] = v.y;
            Bs[lk + 2][lr] = v.z;
            Bs[lk + 3][lr] = v.w;
        }
        __syncthreads();

#pragma unroll
        for (int k = 0; k < 16; k++) {
            float4 bv = *(const float4*)&Bs[k][tx * 4];
            u64 bp0 = pk2(bv.x), bp1 = pk2(bv.y), bp2 = pk2(bv.z), bp3 = pk2(bv.w);
            ulonglong2 a01 = *(const ulonglong2*)&As[k][ty * 8];
            ulonglong2 a23 = *(const ulonglong2*)&As[k][ty * 8 + 4];
            u64 ap[4] = {a01.x, a01.y, a23.x, a23.y};
#pragma unroll
            for (int i = 0; i < 4; i++) {
                fma2(acc[i][0], ap[i], bp0);
                fma2(acc[i][1], ap[i], bp1);
                fma2(acc[i][2], ap[i], bp2);
                fma2(acc[i][3], ap[i], bp3);
            }
        }
        __syncthreads();
    }

    float accf[8][4];
#pragma unroll
    for (int i = 0; i < 4; i++)
#pragma unroll
        for (int j = 0; j < 4; j++) {
            float2 v = up2(acc[i][j]);
            accf[2 * i + 0][j] = v.x;
            accf[2 * i + 1][j] = v.y;
        }

    float bv[4];
    *(float4*)bv = *(const float4*)&bias[n0 + tx * 4];

#pragma unroll
    for (int i = 0; i < 8; i++) {
        int m = m0 + ty * 8 + i;
        if (MODE == 3) {
            int t = m >> 6, b = m & 63;
            float4 c;
            c.x = accf[i][0] + bv[0];
            c.y = accf[i][1] + bv[1];
            c.z = accf[i][2] + bv[2];
            c.w = accf[i][3] + bv[3];
            *(float4*)&out[((size_t)b * S_ + t) * O_ + n0 + tx * 4] = c;
        } else {
            int t = m & (S_ - 1), b = m >> 10;
#pragma unroll
            for (int j = 0; j < 4; j++)
                out[((size_t)t * G3H + n0 + tx * 4 + j) * B_ + b] = accf[i][j] + bv[j];
        }
    }
}

// ---------------------------------------------------------------------------
// Fused two-layer GRU wavefront. 96 CTAs = 3 groups x 32 (16 j each).
//  G0: h0[s] = cell(h0[s-1], gi0[s]);  G1: gi1[s-1] = h0[s-1]@W_ih1^T + b;
//  G2: h1[s-2] = cell(h1[s-3], gi1[s-2]).
// Weights PRE-DUPLICATED as f32x2 pairs in smem (192 KB) -> no MOVs in the
// mainloop. h streamed via 2 x 16 KB cp.async double buffer (8 chunks of 64 k).
// Thread = (kh, jl, bs): k-half x 16 j x 8 b (b = {bs*4..+3, 32+bs*4..+3});
// k-halves interleave even/odd k and reduce once per step via smem.
// smem bytes: hbuf 32768 @0 | Wrz ulonglong2 131072 @32768 | Wn u64 65536 @163840
// ---------------------------------------------------------------------------
#define FUS_SMEM_BYTES 229376

template <int C>
__device__ __forceinline__ void chunk_compute(const float* __restrict__ hb,
                                              const ulonglong2* __restrict__ Wrz,
                                              const u64* __restrict__ Wn,
                                              int kh, int jl, int bA, int bB,
                                              u64* aR, u64* aZ, u64* aN)
{
    asm volatile("cp.async.wait_group %0;" :: "n"(C == 7 ? 0 : 1));
    __syncthreads();
    const float* hbuf = hb + (C & 1) * 4096;
#pragma unroll 8
    for (int i = 0; i < 32; i++) {
        const int kl = kh + 2 * i;
        const int kg = C * 64 + kl;
        ulonglong2 w2 = Wrz[kg * 16 + jl];
        u64 wn        = Wn [kg * 16 + jl];
        ulonglong2 hA = *(const ulonglong2*)&hbuf[kl * 64 + bA];
        ulonglong2 hB = *(const ulonglong2*)&hbuf[kl * 64 + bB];
        fma2(aR[0], hA.x, w2.x); fma2(aR[1], hA.y, w2.x);
        fma2(aR[2], hB.x, w2.x); fma2(aR[3], hB.y, w2.x);
        fma2(aZ[0], hA.x, w2.y); fma2(aZ[1], hA.y, w2.y);
        fma2(aZ[2], hB.x, w2.y); fma2(aZ[3], hB.y, w2.y);
        fma2(aN[0], hA.x, wn);   fma2(aN[1], hA.y, wn);
        fma2(aN[2], hB.x, wn);   fma2(aN[3], hB.y, wn);
    }
}

__device__ __forceinline__ void chunk_issue(float* hb, const float* hsrc,
                                            int c, int tid)
{
    const float* s4 = hsrc + c * 4096;
    float*       d4 = hb + (c & 1) * 4096;
#pragma unroll
    for (int u = 0; u < 4; u++)
        cpa16(d4 + (tid + u * 256) * 4, s4 + (tid + u * 256) * 4);
    asm volatile("cp.async.commit_group;");
}

__global__ void __launch_bounds__(RT, 1)
gru_fused(const float* __restrict__ gi0,
          const float* __restrict__ Whh0, const float* __restrict__ bhh0,
          const float* __restrict__ Wih1, const float* __restrict__ bih1,
          const float* __restrict__ Whh1, const float* __restrict__ bhh1,
          float* __restrict__ hid)    // [2][B][H] tail of d_out
{
    extern __shared__ float sm[];
    float*      hb  = sm;                                   // 32768 B
    ulonglong2* Wrz = (ulonglong2*)((char*)sm + 32768);     // 131072 B
    u64*        Wn  = (u64*)((char*)sm + 163840);           // 65536 B

    const int tid   = threadIdx.x;
    const int cta   = blockIdx.x;
    const int grp   = cta >> 5;
    const int lc    = cta & 31;
    const int jbase = lc * 16;

    const float* Wsrc = (grp == 0) ? Whh0 : (grp == 1) ? Wih1 : Whh1;

    // Pre-duplicated weight preload: 16 j x 512 k x 3 gates as packed f32x2.
    for (int i = tid; i < 16 * 512; i += RT) {
        int k = i & 511, jj = i >> 9;
        int j = jbase + jj;
        float wr = Wsrc[(size_t)j          * 512 + k];
        float wz = Wsrc[(size_t)(512 + j)  * 512 + k];
        float wn = Wsrc[(size_t)(1024 + j) * 512 + k];
        ulonglong2 wp; wp.x = pk2(wr); wp.y = pk2(wz);
        Wrz[k * 16 + jj] = wp;
        Wn [k * 16 + jj] = pk2(wn);
    }

    const int kh = tid >> 7;           // k-half: even/odd k
    const int rm = tid & 127;
    const int jl = rm >> 3;            // 0..15
    const int bs = rm & 7;             // 0..7
    const int bA = bs * 4;             // b group A: [bA, bA+4)
    const int bB = 32 + bs * 4;        // b group B: [bB, bB+4)
    const int j  = jbase + jl;

    float br = 0.f, bz = 0.f, bn = 0.f;
    if (grp == 0) { br = bhh0[j]; bz = bhh0[512 + j]; bn = bhh0[1024 + j]; }
    if (grp == 1) { br = bih1[j]; bz = bih1[512 + j]; bn = bih1[1024 + j]; }
    if (grp == 2) { br = bhh1[j]; bz = bhh1[512 + j]; bn = bhh1[1024 + j]; }

    __syncthreads();

    for (int s = 0; s < STEPS; s++) {
        const bool active = (grp == 0) ? (s < 1024)
                          : (grp == 1) ? (s >= 1 && s < 1025)
                                       : (s >= 2);
        if (active) {
            const float* hsrc = ((grp == 2) ? g_h1T : g_h0T)
                              + (((grp == 2 ? s - 2 : s) + 1) & 1) * (H_ * B_);

            chunk_issue(hb, hsrc, 0, tid);
            chunk_issue(hb, hsrc, 1, tid);

            // Prefetch gi + h_old straight from global (arrives under mainloop)
            float GIR[8], GIZ[8], GIN[8], hold[8];
            if (kh == 0) {
                if (grp != 1) {
                    const float* p = (grp == 0)
                        ? gi0   + (size_t)s * (G3H * 64)
                        : g_gi1 + (size_t)(s & 1) * (G3H * 64);
                    *(float4*)&GIR[0] = *(const float4*)&p[(size_t)j          * 64 + bA];
                    *(float4*)&GIR[4] = *(const float4*)&p[(size_t)j          * 64 + bB];
                    *(float4*)&GIZ[0] = *(const float4*)&p[(size_t)(512 + j)  * 64 + bA];
                    *(float4*)&GIZ[4] = *(const float4*)&p[(size_t)(512 + j)  * 64 + bB];
                    *(float4*)&GIN[0] = *(const float4*)&p[(size_t)(1024 + j) * 64 + bA];
                    *(float4*)&GIN[4] = *(const float4*)&p[(size_t)(1024 + j) * 64 + bB];
                    *(float4*)&hold[0] = *(const float4*)&hsrc[j * 64 + bA];
                    *(float4*)&hold[4] = *(const float4*)&hsrc[j * 64 + bB];
                }
            }

            u64 aR[4] = {0,0,0,0}, aZ[4] = {0,0,0,0}, aN[4] = {0,0,0,0};

            chunk_compute<0>(hb, Wrz, Wn, kh, jl, bA, bB, aR, aZ, aN);
            __syncthreads(); chunk_issue(hb, hsrc, 2, tid);
            chunk_compute<1>(hb, Wrz, Wn, kh, jl, bA, bB, aR, aZ, aN);
            __syncthreads(); chunk_issue(hb, hsrc, 3, tid);
            chunk_compute<2>(hb, Wrz, Wn, kh, jl, bA, bB, aR, aZ, aN);
            __syncthreads(); chunk_issue(hb, hsrc, 4, tid);
            chunk_compute<3>(hb, Wrz, Wn, kh, jl, bA, bB, aR, aZ, aN);
            __syncthreads(); chunk_issue(hb, hsrc, 5, tid);
            chunk_compute<4>(hb, Wrz, Wn, kh, jl, bA, bB, aR, aZ, aN);
            __syncthreads(); chunk_issue(hb, hsrc, 6, tid);
            chunk_compute<5>(hb, Wrz, Wn, kh, jl, bA, bB, aR, aZ, aN);
            __syncthreads(); chunk_issue(hb, hsrc, 7, tid);
            chunk_compute<6>(hb, Wrz, Wn, kh, jl, bA, bB, aR, aZ, aN);
            chunk_compute<7>(hb, Wrz, Wn, kh, jl, bA, bB, aR, aZ, aN);

            // Cross-k-half reduction via smem (hbuf buf0 region is dead now;
            // chunk 7 lives in buf1, untouched by P).
            u64* P = (u64*)hb;
            if (kh == 1) {
                u64* pp = P + (size_t)rm * 12;
#pragma unroll
                for (int q = 0; q < 4; q++) {
                    pp[q]     = aR[q];
                    pp[4 + q] = aZ[q];
                    pp[8 + q] = aN[q];
                }
            }
            __syncthreads();

            if (kh == 0) {
                const u64* pp = P + (size_t)rm * 12;
#pragma unroll
                for (int q = 0; q < 4; q++) {
                    add2(aR[q], pp[q]);
                    add2(aZ[q], pp[4 + q]);
                    add2(aN[q], pp[8 + q]);
                }

                float R[8], Z[8], N[8];
#pragma unroll
                for (int p = 0; p < 4; p++) {
                    float2 r = up2(aR[p]), z = up2(aZ[p]), n = up2(aN[p]);
                    R[2*p] = r.x; R[2*p+1] = r.y;
                    Z[2*p] = z.x; Z[2*p+1] = z.y;
                    N[2*p] = n.x; N[2*p+1] = n.y;
                }

                if (grp == 1) {
                    float* q = g_gi1 + (size_t)((s - 1) & 1) * (G3H * 64);
                    float o[8];
#pragma unroll
                    for (int i = 0; i < 8; i++) o[i] = R[i] + br;
                    *(float4*)&q[(size_t)j * 64 + bA] = *(float4*)&o[0];
                    *(float4*)&q[(size_t)j * 64 + bB] = *(float4*)&o[4];
#pragma unroll
                    for (int i = 0; i < 8; i++) o[i] = Z[i] + bz;
                    *(float4*)&q[(size_t)(512 + j) * 64 + bA] = *(float4*)&o[0];
                    *(float4*)&q[(size_t)(512 + j) * 64 + bB] = *(float4*)&o[4];
#pragma unroll
                    for (int i = 0; i < 8; i++) o[i] = N[i] + bn;
                    *(float4*)&q[(size_t)(1024 + j) * 64 + bA] = *(float4*)&o[0];
                    *(float4*)&q[(size_t)(1024 + j) * 64 + bB] = *(float4*)&o[4];
                } else {
                    float hn[8];
#pragma unroll
                    for (int i = 0; i < 8; i++) {
                        float r_ = sigmoidf_(GIR[i] + R[i] + br);
                        float z_ = sigmoidf_(GIZ[i] + Z[i] + bz);
                        float n_ = tanhf(GIN[i] + r_ * (N[i] + bn));
                        hn[i] = (1.f - z_) * n_ + z_ * hold[i];
                    }

                    const int tau = (grp == 2) ? s - 2 : s;
                    float* hdT = ((grp == 2) ? g_h1T : g_h0T) + (tau & 1) * (H_ * B_);
                    *(float4*)&hdT[j * 64 + bA] = *(float4*)&hn[0];
                    *(float4*)&hdT[j * 64 + bB] = *(float4*)&hn[4];

                    if (grp == 2) {
                        float* hq = g_h1sq + (size_t)tau * (H_ * B_);
                        *(float4*)&hq[j * 64 + bA] = *(float4*)&hn[0];
                        *(float4*)&hq[j * 64 + bB] = *(float4*)&hn[4];
                    }
                    if (tau == S_ - 1) {
                        float* hd = hid + (grp == 2 ? B_ * H_ : 0);
#pragma unroll
                        for (int i = 0; i < 4; i++) {
                            hd[(size_t)(bA + i) * H_ + j] = hn[i];
                            hd[(size_t)(bB + i) * H_ + j] = hn[4 + i];
                        }
                    }
                }
            }
        }

        // ---- two-level grid barrier ----
        __syncthreads();
        if (tid == 0) {
            __threadfence();
            unsigned go = atomicAdd(&g_sync[(cta >> 3) * 32], 1u);
            if (go == (unsigned)(s + 1) * 8 - 1) {
                unsigned ro = atomicAdd(&g_sync[400], 1u);
                if (ro == (unsigned)(s + 1) * 12 - 1) {
                    __threadfence();
                    *((volatile unsigned*)&g_sync[416]) = (unsigned)(s + 1);
                }
            }
            while (*((volatile unsigned*)&g_sync[416]) < (unsigned)(s + 1)) { }
            __threadfence();
        }
        __syncthreads();
    }
}

// ---------------------------------------------------------------------------
// Launch
// ---------------------------------------------------------------------------
extern "C" void kernel_launch(void* const* d_in, const int* in_sizes, int n_in,
                              void* d_out, int out_size)
{
    const float* x    = (const float*)d_in[0];
    const float* Wih0 = (const float*)d_in[1];
    const float* Whh0 = (const float*)d_in[2];
    const float* bih0 = (const float*)d_in[3];
    const float* bhh0 = (const float*)d_in[4];
    const float* Wih1 = (const float*)d_in[5];
    const float* Whh1 = (const float*)d_in[6];
    const float* bih1 = (const float*)d_in[7];
    const float* bhh1 = (const float*)d_in[8];
    const float* Wfc  = (const float*)d_in[9];
    const float* bfc  = (const float*)d_in[10];

    float* out = (float*)d_out;                    // logits [B][S][O]
    float* hid = out + (size_t)B_ * S_ * O_;       // hidden [2][B][H]

    float *gi0, *h1sq, *h0T, *h1T;
    unsigned* sy;
    cudaGetSymbolAddress((void**)&gi0,  g_gi0);
    cudaGetSymbolAddress((void**)&h1sq, g_h1sq);
    cudaGetSymbolAddress((void**)&h0T,  g_h0T);
    cudaGetSymbolAddress((void**)&h1T,  g_h1T);
    cudaGetSymbolAddress((void**)&sy,   g_sync);

    cudaFuncSetAttribute(gru_fused, cudaFuncAttributeMaxDynamicSharedMemorySize,
                         FUS_SMEM_BYTES);

    const int M = B_ * S_;
    dim3 blk(256);
    dim3 gGI(G3H / 64, M / 128);   // 24 x 512
    dim3 gFC(O_ / 64, M / 128);    //  8 x 512

    // gi0 = x @ W_ih0^T + b_ih0   -> [t][row][b]
    sgemm_bias<0><<<gGI, blk>>>(x, Wih0, bih0, gi0, M, G3H, I_);

    cudaMemsetAsync(h0T, 0, (size_t)2 * H_ * B_ * sizeof(float));
    cudaMemsetAsync(h1T, 0, (size_t)2 * H_ * B_ * sizeof(float));
    cudaMemsetAsync(sy, 0, 512 * sizeof(unsigned));

    gru_fused<<<GR, RT, FUS_SMEM_BYTES>>>(gi0, Whh0, bhh0, Wih1, bih1,
                                          Whh1, bhh1, hid);

    // logits = hseq1 @ W_fc^T + b_fc   (A read from transposed [t][j][b])
    sgemm_bias<3><<<gFC, blk>>>(h1sq, Wfc, bfc, out, M, O_, H_);
}